// round 16
// baseline (speedup 1.0000x reference)
#include <cuda_runtime.h>
#include <math_constants.h>

// pcd [8, 4096, 3] f32, k = 5 (compile-time)
#define N_PTS    4096
#define BATCHES  8
#define QPB      256        // queries per block
#define QPT      4          // queries per thread (register candidate reuse)
#define KTHREADS 256        // (QPB/QPT) groups x 4 quarters
#define QUARTER  1024

typedef unsigned long long ull;

// ---- packed f32x2 helpers -------------------------------------------------
__device__ __forceinline__ ull mul2(ull a, ull b) {
    ull r; asm("mul.rn.f32x2 %0,%1,%2;" : "=l"(r) : "l"(a), "l"(b)); return r;
}
__device__ __forceinline__ ull fma2(ull a, ull b, ull c) {
    ull r; asm("fma.rn.f32x2 %0,%1,%2,%3;" : "=l"(r) : "l"(a), "l"(b), "l"(c)); return r;
}
__device__ __forceinline__ ull pack2(float lo, float hi) {
    ull r; asm("mov.b64 %0,{%1,%2};" : "=l"(r) : "f"(lo), "f"(hi)); return r;
}
__device__ __forceinline__ void unpack2(ull v, float& lo, float& hi) {
    asm("mov.b64 {%0,%1},%2;" : "=f"(lo), "=f"(hi) : "l"(v));
}

// Strict-'<' sorted top-5 insert (ascending-j scan => stable low-index ties).
__device__ __forceinline__ void ins5(float e, int j, float le[5], int li[5])
{
    if (e < le[4]) {
        const bool p3 = e < le[3], p2 = e < le[2], p1 = e < le[1],
                   p0 = e < le[0];
        le[4] = p3 ? le[3] : e;              li[4] = p3 ? li[3] : j;
        le[3] = p3 ? (p2 ? le[2] : e) : le[3]; li[3] = p3 ? (p2 ? li[2] : j) : li[3];
        le[2] = p2 ? (p1 ? le[1] : e) : le[2]; li[2] = p2 ? (p1 ? li[1] : j) : li[2];
        le[1] = p1 ? (p0 ? le[0] : e) : le[1]; li[1] = p1 ? (p0 ? li[0] : j) : li[1];
        le[0] = p0 ? e : le[0];              li[0] = p0 ? j : li[0];
    }
}

// ---------------------------------------------------------------------------
// knn+trace with register candidate reuse.
// Block = 256 queries of one batch; whole cloud in smem SoA (x,y,z,|p|^2).
// Thread (grp, qtr): handles the 4 queries {grp, grp+64, grp+128, grp+192}
// (block-local) over candidate quarter [1024*qtr, 1024*(qtr+1)).
// Each 8-candidate chunk is loaded ONCE (8 broadcast LDS.128 — warps have
// uniform qtr) and evaluated against all 4 register-resident queries: smem
// traffic per eval drops 16B -> 4B, lifting the measured crossbar wall
// (~74us) to ~19us. Per-query chunk-min filter + strict-'<' insert as R13.
// Quarters 1-3 publish lists; quarter 0 merges (lower quarter preferred on
// ties = exact jax.lax.top_k order), computes covariance trace, writes.
// ---------------------------------------------------------------------------
__global__ void __launch_bounds__(KTHREADS, 1)
knn_trace_kernel(const float* __restrict__ pcd, float* __restrict__ out)
{
    extern __shared__ float sm[];
    float* Xs = sm;
    float* Ys = sm + N_PTS;
    float* Zs = sm + 2 * N_PTS;
    float* Ws = sm + 3 * N_PTS;
    float2* mbv = reinterpret_cast<float2*>(sm + 4 * N_PTS);  // [3][QPB][5]

    const int b   = blockIdx.y;
    const int q0  = blockIdx.x * QPB;
    const int tid = threadIdx.x;
    const float* __restrict__ P = pcd + (size_t)b * N_PTS * 3;

    for (int p = tid; p < N_PTS; p += KTHREADS) {
        const float x = P[3 * p + 0];
        const float y = P[3 * p + 1];
        const float z = P[3 * p + 2];
        Xs[p] = x; Ys[p] = y; Zs[p] = z;
        Ws[p] = fmaf(z, z, fmaf(y, y, x * x));
    }
    __syncthreads();

    const int grp = tid & 63;          // query group (queries grp + 64*q)
    const int qtr = tid >> 6;          // candidate quarter (uniform per warp)

    // Register-resident query coords (packed for f32x2)
    ull ax2[QPT], ay2[QPT], az2[QPT];
    #pragma unroll
    for (int q = 0; q < QPT; ++q) {
        const int qi = q0 + grp + (q << 6);
        const float ax = Xs[qi], ay = Ys[qi], az = Zs[qi];
        ax2[q] = pack2(ax, ax); ay2[q] = pack2(ay, ay); az2[q] = pack2(az, az);
    }
    const ull m2 = pack2(-2.0f, -2.0f);

    float le[QPT][5];
    int   li[QPT][5];
    #pragma unroll
    for (int q = 0; q < QPT; ++q)
        #pragma unroll
        for (int s = 0; s < 5; ++s) { le[q][s] = CUDART_INF_F; li[q][s] = 0; }

    const ulonglong2* X2 = reinterpret_cast<const ulonglong2*>(Xs);
    const ulonglong2* Y2 = reinterpret_cast<const ulonglong2*>(Ys);
    const ulonglong2* Z2 = reinterpret_cast<const ulonglong2*>(Zs);
    const ulonglong2* W2 = reinterpret_cast<const ulonglong2*>(Ws);

    const int jbase = qtr * QUARTER;

    #pragma unroll 2
    for (int jj = 0; jj < QUARTER; jj += 8) {
        const int i4 = (jbase + jj) >> 2;      // uniform across warp -> broadcast

        // Load chunk ONCE (8 candidates, 128B)
        const ulonglong2 x0 = X2[i4], x1 = X2[i4 + 1];
        const ulonglong2 y0 = Y2[i4], y1 = Y2[i4 + 1];
        const ulonglong2 z0 = Z2[i4], z1 = Z2[i4 + 1];
        const ulonglong2 w0 = W2[i4], w1 = W2[i4 + 1];

        // Evaluate against all 4 register queries
        #pragma unroll
        for (int q = 0; q < QPT; ++q) {
            ull t0 = fma2(m2, fma2(az2[q], z0.x, fma2(ay2[q], y0.x, mul2(ax2[q], x0.x))), w0.x);
            ull t1 = fma2(m2, fma2(az2[q], z0.y, fma2(ay2[q], y0.y, mul2(ax2[q], x0.y))), w0.y);
            ull t2 = fma2(m2, fma2(az2[q], z1.x, fma2(ay2[q], y1.x, mul2(ax2[q], x1.x))), w1.x);
            ull t3 = fma2(m2, fma2(az2[q], z1.y, fma2(ay2[q], y1.y, mul2(ax2[q], x1.y))), w1.y);

            float e0, e1, e2, e3, e4, e5, e6, e7;
            unpack2(t0, e0, e1); unpack2(t1, e2, e3);
            unpack2(t2, e4, e5); unpack2(t3, e6, e7);

            const float m8 = fminf(fminf(fminf(e0, e1), fminf(e2, e3)),
                                   fminf(fminf(e4, e5), fminf(e6, e7)));
            if (m8 < le[q][4]) {                  // strict-< insert can fire
                const int j = jbase + jj;
                ins5(e0, j + 0, le[q], li[q]); ins5(e1, j + 1, le[q], li[q]);
                ins5(e2, j + 2, le[q], li[q]); ins5(e3, j + 3, le[q], li[q]);
                ins5(e4, j + 4, le[q], li[q]); ins5(e5, j + 5, le[q], li[q]);
                ins5(e6, j + 6, le[q], li[q]); ins5(e7, j + 7, le[q], li[q]);
            }
        }
    }

    // Quarters 1-3 publish sorted 5-lists for their 4 queries.
    if (qtr != 0) {
        #pragma unroll
        for (int q = 0; q < QPT; ++q) {
            const int qlocal = grp + (q << 6);
            float2* row = &mbv[((qtr - 1) * QPB + qlocal) * 5];
            #pragma unroll
            for (int s = 0; s < 5; ++s)
                row[s] = make_float2(le[q][s], __int_as_float(li[q][s]));
        }
    }
    __syncthreads();

    if (qtr == 0) {
        #pragma unroll
        for (int q = 0; q < QPT; ++q) {
            const int qlocal = grp + (q << 6);

            float fe[6]; int fi[6];
            #pragma unroll
            for (int s = 0; s < 5; ++s) { fe[s] = le[q][s]; fi[s] = li[q][s]; }
            fe[5] = CUDART_INF_F; fi[5] = 0x7FFFFFFF;

            // Merge quarters 1..3 in order; '<=' keeps the lower quarter
            // (lower index range) on ties -> top_k stable order.
            #pragma unroll
            for (int qq = 0; qq < 3; ++qq) {
                float ge[6]; int gi[6];
                const float2* row = &mbv[(qq * QPB + qlocal) * 5];
                #pragma unroll
                for (int s = 0; s < 5; ++s) {
                    const float2 r = row[s];
                    ge[s] = r.x; gi[s] = __float_as_int(r.y);
                }
                ge[5] = CUDART_INF_F; gi[5] = 0x7FFFFFFF;

                float me[5]; int mi[5];
                int ia = 0, ib = 0;
                #pragma unroll
                for (int s = 0; s < 5; ++s) {
                    const bool takeA = fe[ia] <= ge[ib];
                    me[s] = takeA ? fe[ia] : ge[ib];
                    mi[s] = takeA ? fi[ia] : gi[ib];
                    ia += takeA ? 1 : 0;
                    ib += takeA ? 0 : 1;
                }
                #pragma unroll
                for (int s = 0; s < 5; ++s) { fe[s] = me[s]; fi[s] = mi[s]; }
                fe[5] = CUDART_INF_F; fi[5] = 0x7FFFFFFF;
            }

            // trace(cov) = sum of squared deviations from centroid / (k-1)
            float xs[5], ys[5], zs[5];
            #pragma unroll
            for (int s = 0; s < 5; ++s) {
                xs[s] = Xs[fi[s]]; ys[s] = Ys[fi[s]]; zs[s] = Zs[fi[s]];
            }
            const float cx = (xs[0] + xs[1] + xs[2] + xs[3] + xs[4]) * 0.2f;
            const float cy = (ys[0] + ys[1] + ys[2] + ys[3] + ys[4]) * 0.2f;
            const float cz = (zs[0] + zs[1] + zs[2] + zs[3] + zs[4]) * 0.2f;
            float tr = 0.0f;
            #pragma unroll
            for (int s = 0; s < 5; ++s) {
                const float dx = xs[s] - cx, dy = ys[s] - cy, dz = zs[s] - cz;
                tr += dx * dx + dy * dy + dz * dz;
            }
            out[(size_t)b * N_PTS + q0 + qlocal] = tr * 0.25f;   // / (k-1)
        }
    }
}

// ---------------------------------------------------------------------------
// Per-batch normalization: curvature = trace / (sum + 1e-8)
// ---------------------------------------------------------------------------
__global__ void __launch_bounds__(1024)
normalize_kernel(float* __restrict__ out)
{
    __shared__ float red[32];
    const int b = blockIdx.x;
    float* __restrict__ o = out + (size_t)b * N_PTS;

    float vals[4];
    float s = 0.0f;
    #pragma unroll
    for (int r = 0; r < 4; ++r) {
        vals[r] = o[threadIdx.x + r * 1024];
        s += vals[r];
    }
    #pragma unroll
    for (int off = 16; off; off >>= 1)
        s += __shfl_xor_sync(0xFFFFFFFFu, s, off);
    if ((threadIdx.x & 31) == 0)
        red[threadIdx.x >> 5] = s;
    __syncthreads();

    if (threadIdx.x < 32) {
        float v = red[threadIdx.x];
        #pragma unroll
        for (int off = 16; off; off >>= 1)
            v += __shfl_xor_sync(0xFFFFFFFFu, v, off);
        if (threadIdx.x == 0) red[0] = v;
    }
    __syncthreads();

    const float denom = red[0] + 1e-8f;
    #pragma unroll
    for (int r = 0; r < 4; ++r)
        o[threadIdx.x + r * 1024] = vals[r] / denom;
}

// ---------------------------------------------------------------------------
extern "C" void kernel_launch(void* const* d_in, const int* in_sizes, int n_in,
                              void* d_out, int out_size)
{
    const float* pcd = (const float*)d_in[0];
    float* out = (float*)d_out;

    const int smem = 4 * N_PTS * sizeof(float)          // SoA cloud (64 KB)
                   + 3 * QPB * 5 * sizeof(float2);      // merge lists (30 KB)
    cudaFuncSetAttribute(knn_trace_kernel,
                         cudaFuncAttributeMaxDynamicSharedMemorySize, smem);

    dim3 grid(N_PTS / QPB, BATCHES);                    // 16 x 8 = 128 blocks
    knn_trace_kernel<<<grid, KTHREADS, smem>>>(pcd, out);
    normalize_kernel<<<BATCHES, 1024>>>(out);
}